// round 17
// baseline (speedup 1.0000x reference)
#include <cuda_runtime.h>
#include <math.h>
#include <stdint.h>

// Problem constants
#define BB 64
#define TT 512
#define CC 384
#define HH 64

// Scratch for Q, K, V projections (8 MB each) — device globals, no allocation.
__device__ float g_q[BB * TT * HH];
__device__ float g_k[BB * TT * HH];
__device__ float g_v[BB * TT * HH];

// ---------------------------------------------------------------------------
// tf32 helpers
// ---------------------------------------------------------------------------
__device__ __forceinline__ uint32_t f2tf32(float f) {
    uint32_t u;
    asm("cvt.rna.tf32.f32 %0, %1;" : "=r"(u) : "f"(f));
    return u;
}

__device__ __forceinline__ void mma_tf32_(float c[4], const uint32_t a[4],
                                          uint32_t b0, uint32_t b1) {
    asm volatile(
        "mma.sync.aligned.m16n8k8.row.col.f32.tf32.tf32.f32 "
        "{%0,%1,%2,%3}, {%4,%5,%6,%7}, {%8,%9}, {%0,%1,%2,%3};\n"
        : "+f"(c[0]), "+f"(c[1]), "+f"(c[2]), "+f"(c[3])
        : "r"(a[0]), "r"(a[1]), "r"(a[2]), "r"(a[3]), "r"(b0), "r"(b1));
}

// ---------------------------------------------------------------------------
// Fused QKV projection (tensor cores, tf32):
//   q/k/v[m, h] = sum_c x[m, c] * W{q,k,v}[c, h]
// Grid: M/64 = 512 blocks. Block 128 threads = 4 warps; warp w owns rows
// [w*16, w*16+16) of the 64-row tile. Each x k-chunk is loaded into smem ONCE
// and reused by all three weight matrices (3 accumulator sets per thread).
// Same mma order per output as the unfused version -> bitwise identical.
// ---------------------------------------------------------------------------
#define XS_ST 36   // A-frag bank = (g*36 + t) % 32 = g*4 + t -> 32 distinct
#define WS_ST 72   // B-frag bank = (t*72 + j*8 + g) % 32 = (t*8 + g + j*8) % 32 -> 32 distinct

__global__ __launch_bounds__(128) void proj_fused_kernel(
    const float* __restrict__ x,
    const float* __restrict__ Wq,
    const float* __restrict__ Wk,
    const float* __restrict__ Wv)
{
    __shared__ __align__(16) uint32_t xs[64][XS_ST];      // x chunk (tf32), [m][k]
    __shared__ __align__(16) uint32_t ws[3][32][WS_ST];   // Wq/Wk/Wv chunks (tf32), [k][n]

    const int tid  = threadIdx.x;
    const int w    = tid >> 5;
    const int lane = tid & 31;
    const int g    = lane >> 2;       // 0..7
    const int t    = lane & 3;        // 0..3
    const int m0   = (int)blockIdx.x * 64;
    const int mw   = w * 16;          // warp's 16-row strip

    const float* Ws[3] = {Wq, Wk, Wv};

    float cf[3][8][4];                // [which][n-tile][frag]
#pragma unroll
    for (int q = 0; q < 3; q++)
#pragma unroll
        for (int j = 0; j < 8; j++)
#pragma unroll
            for (int i = 0; i < 4; i++) cf[q][j][i] = 0.f;

    // thread-static load coords
    const int xc4 = (tid & 7) * 4;    // k col (float4) for x chunk
    const int xr0 = tid >> 3;         // row base (0..15) for x chunk
    const int wc4 = (tid & 15) * 4;   // n col (float4) for W chunks
    const int wr0 = tid >> 4;         // k row base (0..7) for W chunks

    for (int k0 = 0; k0 < CC; k0 += 32) {
        // Load x chunk 64x32 ONCE (coalesced float4), cvt tf32
#pragma unroll
        for (int rr = xr0; rr < 64; rr += 16) {
            const float4 v = *(const float4*)&x[(size_t)(m0 + rr) * CC + k0 + xc4];
            uint4 u;
            u.x = f2tf32(v.x); u.y = f2tf32(v.y);
            u.z = f2tf32(v.z); u.w = f2tf32(v.w);
            *(uint4*)&xs[rr][xc4] = u;
        }
        // Load all three W chunks 32x64
#pragma unroll
        for (int q = 0; q < 3; q++) {
            const float* W = Ws[q];
#pragma unroll
            for (int rr = wr0; rr < 32; rr += 8) {
                const float4 v = *(const float4*)&W[(k0 + rr) * HH + wc4];
                uint4 u;
                u.x = f2tf32(v.x); u.y = f2tf32(v.y);
                u.z = f2tf32(v.z); u.w = f2tf32(v.w);
                *(uint4*)&ws[q][rr][wc4] = u;
            }
        }
        __syncthreads();

#pragma unroll
        for (int ks = 0; ks < 32; ks += 8) {
            uint32_t a[4];
            a[0] = xs[mw + g    ][ks + t    ];
            a[1] = xs[mw + g + 8][ks + t    ];
            a[2] = xs[mw + g    ][ks + t + 4];
            a[3] = xs[mw + g + 8][ks + t + 4];
#pragma unroll
            for (int q = 0; q < 3; q++) {
#pragma unroll
                for (int j = 0; j < 8; j++) {
                    const uint32_t b0 = ws[q][ks + t    ][j * 8 + g];
                    const uint32_t b1 = ws[q][ks + t + 4][j * 8 + g];
                    mma_tf32_(cf[q][j], a, b0, b1);
                }
            }
        }
        __syncthreads();
    }

    // Store all three outputs. Frag c0,c1 -> (row, 2t..); c2,c3 -> row+8.
    float* outs[3] = {g_q, g_k, g_v};
#pragma unroll
    for (int q = 0; q < 3; q++) {
        float* outp = outs[q];
#pragma unroll
        for (int j = 0; j < 8; j++) {
            const int row = m0 + mw + g;
            const int col = j * 8 + 2 * t;
            float2 lo, hi;
            lo.x = cf[q][j][0]; lo.y = cf[q][j][1];
            hi.x = cf[q][j][2]; hi.y = cf[q][j][3];
            *(float2*)&outp[(size_t)row * HH + col]       = lo;
            *(float2*)&outp[(size_t)(row + 8) * HH + col] = hi;
        }
    }
}

// ---------------------------------------------------------------------------
// Tensor-core flash attention (tf32 m16n8k8). Unchanged from R14 (42.4us).
// Grid: (T/64 q-tiles, B). Block 128 threads = 4 warps; warp w owns q rows
// [w*16, w*16+16). Q in A-fragments (scale folded). Per kv tile: S via 64
// mmas, softmax on C-fragments, P -> warp-private smem (tf32), PV via 64 mmas.
// ---------------------------------------------------------------------------
#define KV_ST 68
#define P_ST  72

__global__ __launch_bounds__(128) void attn_kernel(float* __restrict__ out)
{
    extern __shared__ __align__(16) uint32_t smu[];
    uint32_t (*Ks)[KV_ST] = (uint32_t(*)[KV_ST])smu;                // [64][68] K natural (tf32)
    uint32_t (*Vs)[KV_ST] = (uint32_t(*)[KV_ST])(smu + 64 * KV_ST); // [64][68] V natural (tf32)

    const int qt  = (int)gridDim.x - 1 - (int)blockIdx.x;  // heavy tiles first
    const int b   = blockIdx.y;
    const int tid = threadIdx.x;
    const int w   = tid >> 5;
    const int lane = tid & 31;
    const int g   = lane >> 2;   // 0..7
    const int t   = lane & 3;    // 0..3

    uint32_t* Pw = smu + 2 * 64 * KV_ST + w * 16 * P_ST;   // warp-private [16][72]

    // Q A-fragments, one per k-step (headdim/8), scale folded. Loaded once.
    uint32_t aq[8][4];
    {
        const float* qb = g_q + ((size_t)b * TT + qt * 64 + w * 16) * HH;
#pragma unroll
        for (int k = 0; k < 8; k++) {
            aq[k][0] = f2tf32(qb[(g    ) * HH + k * 8 + t    ] * 0.125f);
            aq[k][1] = f2tf32(qb[(g + 8) * HH + k * 8 + t    ] * 0.125f);
            aq[k][2] = f2tf32(qb[(g    ) * HH + k * 8 + t + 4] * 0.125f);
            aq[k][3] = f2tf32(qb[(g + 8) * HH + k * 8 + t + 4] * 0.125f);
        }
    }

    float m0 = -1e30f, m1 = -1e30f, l0 = 0.f, l1 = 0.f;
    float of[8][4];
#pragma unroll
    for (int j = 0; j < 8; j++)
#pragma unroll
        for (int i = 0; i < 4; i++) of[j][i] = 0.f;

    for (int kt = 0; kt <= qt; kt++) {
        __syncthreads();  // prior tile's K/V reads complete before overwrite

        // Cooperative load of K and V tiles (natural [key][h], tf32 bits)
        {
            const float* kb = g_k + ((size_t)b * TT + kt * 64) * HH;
            const float* vb = g_v + ((size_t)b * TT + kt * 64) * HH;
#pragma unroll
            for (int i = tid; i < 64 * 16; i += 128) {
                const int row = i >> 4;
                const int c4  = (i & 15) * 4;
                float4 kv = *(const float4*)&kb[row * HH + c4];
                uint4 u;
                u.x = f2tf32(kv.x); u.y = f2tf32(kv.y);
                u.z = f2tf32(kv.z); u.w = f2tf32(kv.w);
                *(uint4*)&Ks[row][c4] = u;
                kv = *(const float4*)&vb[row * HH + c4];
                u.x = f2tf32(kv.x); u.y = f2tf32(kv.y);
                u.z = f2tf32(kv.z); u.w = f2tf32(kv.w);
                *(uint4*)&Vs[row][c4] = u;
            }
        }
        __syncthreads();

        // ---- S = Q K^T : 8 n-tiles (keys) x 8 k-steps (headdim) ----
        float sc[8][4];
#pragma unroll
        for (int j = 0; j < 8; j++)
#pragma unroll
            for (int i = 0; i < 4; i++) sc[j][i] = 0.f;

#pragma unroll
        for (int k = 0; k < 8; k++) {
#pragma unroll
            for (int j = 0; j < 8; j++) {
                const uint32_t b0 = Ks[j * 8 + g][k * 8 + t    ];
                const uint32_t b1 = Ks[j * 8 + g][k * 8 + t + 4];
                mma_tf32_(sc[j], aq[k], b0, b1);
            }
        }

        // ---- causal mask (diagonal tile only) ----
        if (kt == qt) {
            const int r0 = w * 16 + g;
            const int r1 = r0 + 8;
#pragma unroll
            for (int j = 0; j < 8; j++) {
                const int c0 = j * 8 + 2 * t;
                if (c0     > r0) sc[j][0] = -1e30f;
                if (c0 + 1 > r0) sc[j][1] = -1e30f;
                if (c0     > r1) sc[j][2] = -1e30f;
                if (c0 + 1 > r1) sc[j][3] = -1e30f;
            }
        }

        // ---- online softmax on C-fragments ----
        float mx0 = -1e30f, mx1 = -1e30f;
#pragma unroll
        for (int j = 0; j < 8; j++) {
            mx0 = fmaxf(mx0, fmaxf(sc[j][0], sc[j][1]));
            mx1 = fmaxf(mx1, fmaxf(sc[j][2], sc[j][3]));
        }
        mx0 = fmaxf(mx0, __shfl_xor_sync(0xffffffffu, mx0, 1));
        mx0 = fmaxf(mx0, __shfl_xor_sync(0xffffffffu, mx0, 2));
        mx1 = fmaxf(mx1, __shfl_xor_sync(0xffffffffu, mx1, 1));
        mx1 = fmaxf(mx1, __shfl_xor_sync(0xffffffffu, mx1, 2));

        const float mn0 = fmaxf(m0, mx0);
        const float mn1 = fmaxf(m1, mx1);
        const float al0 = __expf(m0 - mn0);
        const float al1 = __expf(m1 - mn1);
        m0 = mn0; m1 = mn1;

        float rs0 = 0.f, rs1 = 0.f;
#pragma unroll
        for (int j = 0; j < 8; j++) {
            const float p00 = __expf(sc[j][0] - m0);
            const float p01 = __expf(sc[j][1] - m0);
            const float p10 = __expf(sc[j][2] - m1);
            const float p11 = __expf(sc[j][3] - m1);
            rs0 += p00 + p01;
            rs1 += p10 + p11;
            uint2 u;
            u.x = f2tf32(p00); u.y = f2tf32(p01);
            *(uint2*)&Pw[(g    ) * P_ST + j * 8 + 2 * t] = u;
            u.x = f2tf32(p10); u.y = f2tf32(p11);
            *(uint2*)&Pw[(g + 8) * P_ST + j * 8 + 2 * t] = u;
            of[j][0] *= al0; of[j][1] *= al0;
            of[j][2] *= al1; of[j][3] *= al1;
        }
        rs0 += __shfl_xor_sync(0xffffffffu, rs0, 1);
        rs0 += __shfl_xor_sync(0xffffffffu, rs0, 2);
        rs1 += __shfl_xor_sync(0xffffffffu, rs1, 1);
        rs1 += __shfl_xor_sync(0xffffffffu, rs1, 2);
        l0 = l0 * al0 + rs0;
        l1 = l1 * al1 + rs1;

        __syncwarp();  // Pw is warp-private; make P visible to all lanes

        // ---- O += P @ V : 8 k-steps (keys) x 8 n-tiles (headdim) ----
#pragma unroll
        for (int k = 0; k < 8; k++) {
            uint32_t pa[4];
            pa[0] = Pw[(g    ) * P_ST + k * 8 + t    ];
            pa[1] = Pw[(g + 8) * P_ST + k * 8 + t    ];
            pa[2] = Pw[(g    ) * P_ST + k * 8 + t + 4];
            pa[3] = Pw[(g + 8) * P_ST + k * 8 + t + 4];
#pragma unroll
            for (int j = 0; j < 8; j++) {
                const uint32_t b0 = Vs[k * 8 + t    ][j * 8 + g];
                const uint32_t b1 = Vs[k * 8 + t + 4][j * 8 + g];
                mma_tf32_(of[j], pa, b0, b1);
            }
        }
    }

    // ---- epilogue: normalize and store ----
    const float inv0 = 1.f / l0;
    const float inv1 = 1.f / l1;
    float* ob = out + ((size_t)b * TT + qt * 64 + w * 16) * HH;
#pragma unroll
    for (int j = 0; j < 8; j++) {
        float2 r;
        r.x = of[j][0] * inv0; r.y = of[j][1] * inv0;
        *(float2*)&ob[(g    ) * HH + j * 8 + 2 * t] = r;
        r.x = of[j][2] * inv1; r.y = of[j][3] * inv1;
        *(float2*)&ob[(g + 8) * HH + j * 8 + 2 * t] = r;
    }
}

// ---------------------------------------------------------------------------
// Launch
// ---------------------------------------------------------------------------
extern "C" void kernel_launch(void* const* d_in, const int* in_sizes, int n_in,
                              void* d_out, int out_size)
{
    const float* x  = (const float*)d_in[0];
    const float* Wq = (const float*)d_in[1];
    const float* Wk = (const float*)d_in[2];
    const float* Wv = (const float*)d_in[3];
    float* out = (float*)d_out;

    (void)in_sizes; (void)n_in; (void)out_size;

    // Fused QKV projection (tf32 tensor cores, x loaded once)
    proj_fused_kernel<<<BB * TT / 64, 128>>>(x, Wq, Wk, Wv);

    // Fused attention (tf32 tensor cores)
    {
        const int smem_bytes = (2 * 64 * KV_ST + 4 * 16 * P_ST) * (int)sizeof(uint32_t);
        cudaFuncSetAttribute(attn_kernel, cudaFuncAttributeMaxDynamicSharedMemorySize, smem_bytes);
        dim3 grid(TT / 64, BB);
        attn_kernel<<<grid, 128, smem_bytes>>>(out);
    }
}